// round 1
// baseline (speedup 1.0000x reference)
#include <cuda_runtime.h>
#include <cuda_bf16.h>
#include <cstdint>

#define Bb 2
#define Nn 2048
#define DIMd 512
#define Hh 8
#define DHd 64
#define Kk 32
#define SCALEf 0.125f
#define NEG_HUGE (-3.402823466e+38f)

// ---------------- scratch (static device globals; no allocation) ----------------
__device__ float g_q[Bb * Nn * (Hh * DHd)];     // (b*N+i, h*64+d)   8 MB
__device__ float g_kv[Bb * Nn * (2 * DHd)];     // (b*N+i, 0..63=k, 64..127=v) 2 MB
__device__ float g_local[Bb * Hh * Nn * DHd];   // ((b*H+h)*N+i)*64+d 8 MB
__device__ float g_comb[Bb * Nn * (Hh * DHd)];  // (b*N+i, h*64+d)   8 MB
__device__ unsigned char g_mask[Bb * Hh * Nn * Kk]; // 1 MB
__device__ int g_mask_mode;

// ---------------- mask dtype detection ----------------
__global__ void detect_mask_kernel(const unsigned int* __restrict__ raw) {
    __shared__ int cf, ch;
    if (threadIdx.x == 0) { cf = 0; ch = 0; }
    __syncthreads();
    int lf = 0, lh = 0;
    for (int idx = threadIdx.x; idx < 4096; idx += 256) {
        unsigned w = raw[idx];
        if (w == 0x3f800000u) lf++;
        if (w & 0xFFFFFF00u) lh++;
    }
    atomicAdd(&cf, lf);
    atomicAdd(&ch, lh);
    __syncthreads();
    if (threadIdx.x == 0) {
        int mode;
        if (cf > 64) mode = 2;        // float32 0/1
        else if (ch > 64) mode = 0;   // bool bytes
        else mode = 1;                // int32 0/1
        g_mask_mode = mode;
    }
}

__global__ void expand_mask_kernel(const void* __restrict__ raw, int n) {
    int idx = blockIdx.x * blockDim.x + threadIdx.x;
    if (idx >= n) return;
    int mode = g_mask_mode;
    unsigned char v;
    if (mode == 0)      v = ((const unsigned char*)raw)[idx] != 0;
    else if (mode == 1) v = ((const int*)raw)[idx] != 0;
    else                v = (((const float*)raw)[idx] != 0.0f);
    g_mask[idx] = v;
}

// ---------------- tiled fp32 GEMM: C[M,Nc] = A[M,K] @ B[K,Nc] (+bias) ----------------
// BM=BN=64, BK=32, 256 threads, 4x4 register micro-tiles.
__global__ void sgemm_kernel(const float* __restrict__ A, const float* __restrict__ Bm,
                             const float* __restrict__ bias, float* __restrict__ C,
                             int M, int Nc, int Kd) {
    __shared__ float As[32 * 64]; // transposed: As[k][m]
    __shared__ float Bs[32 * 64]; // Bs[k][n]
    int tid = threadIdx.x;
    int ty = tid >> 4, tx = tid & 15;
    int rowBase = blockIdx.y * 64;
    int colBase = blockIdx.x * 64;
    float acc[4][4] = {};

    for (int k0 = 0; k0 < Kd; k0 += 32) {
        // A tile 64x32 -> transposed smem
#pragma unroll
        for (int rep = 0; rep < 2; rep++) {
            int e = tid + rep * 256;
            int r = e >> 3, k4 = (e & 7) * 4;
            float4 a = *(const float4*)&A[(size_t)(rowBase + r) * Kd + k0 + k4];
            As[(k4 + 0) * 64 + r] = a.x;
            As[(k4 + 1) * 64 + r] = a.y;
            As[(k4 + 2) * 64 + r] = a.z;
            As[(k4 + 3) * 64 + r] = a.w;
        }
        // B tile 32x64 -> natural smem
#pragma unroll
        for (int rep = 0; rep < 2; rep++) {
            int e = tid + rep * 256;
            int kk = e >> 4, c4 = (e & 15) * 4;
            *(float4*)&Bs[kk * 64 + c4] =
                *(const float4*)&Bm[(size_t)(k0 + kk) * Nc + colBase + c4];
        }
        __syncthreads();
#pragma unroll
        for (int kk = 0; kk < 32; kk++) {
            float4 a4 = *(const float4*)&As[kk * 64 + ty * 4];
            float4 b4 = *(const float4*)&Bs[kk * 64 + tx * 4];
            float av[4] = {a4.x, a4.y, a4.z, a4.w};
            float bv[4] = {b4.x, b4.y, b4.z, b4.w};
#pragma unroll
            for (int i = 0; i < 4; i++)
#pragma unroll
                for (int j = 0; j < 4; j++)
                    acc[i][j] = fmaf(av[i], bv[j], acc[i][j]);
        }
        __syncthreads();
    }

    float bv[4] = {0.f, 0.f, 0.f, 0.f};
    if (bias) {
#pragma unroll
        for (int j = 0; j < 4; j++) bv[j] = bias[colBase + tx * 4 + j];
    }
#pragma unroll
    for (int i = 0; i < 4; i++) {
        float4 o;
        o.x = acc[i][0] + bv[0];
        o.y = acc[i][1] + bv[1];
        o.z = acc[i][2] + bv[2];
        o.w = acc[i][3] + bv[3];
        *(float4*)&C[(size_t)(rowBase + ty * 4 + i) * Nc + colBase + tx * 4] = o;
    }
}

// ---------------- local causal flash attention ----------------
// grid (32, B*H), 256 threads. Tiles: Q 64x64, K/V 64x64. P aliases K buffer.
__global__ void flash_local_kernel(const float* __restrict__ q,
                                   const float* __restrict__ kv,
                                   float* __restrict__ localOut) {
    __shared__ float Qt[64 * 64];   // Qt[d][r]
    __shared__ float KPt[64 * 64];  // Kt[d][c]  then  Pt[c][r]
    __shared__ float Vs[64 * 64];   // Vs[c][d]

    int tid = threadIdx.x;
    int ty = tid >> 4, tx = tid & 15;
    int bh = blockIdx.y;
    int b = bh >> 3;
    int qb = 31 - blockIdx.x;     // heavy blocks first
    int i0 = qb * 64;
    int h = bh & 7;

    // load Q tile transposed
#pragma unroll
    for (int rep = 0; rep < 4; rep++) {
        int e = tid + rep * 256;
        int r = e >> 4, d4 = (e & 15) * 4;
        float4 a = *(const float4*)&q[(size_t)(b * Nn + i0 + r) * 512 + h * 64 + d4];
        Qt[(d4 + 0) * 64 + r] = a.x;
        Qt[(d4 + 1) * 64 + r] = a.y;
        Qt[(d4 + 2) * 64 + r] = a.z;
        Qt[(d4 + 3) * 64 + r] = a.w;
    }

    float o[4][4] = {};
    float m_i[4], l_i[4];
#pragma unroll
    for (int i = 0; i < 4; i++) { m_i[i] = NEG_HUGE; l_i[i] = 0.f; }
    __syncthreads();

    for (int jb = 0; jb <= qb; jb++) {
        int j0 = jb * 64;
        // load K transposed + V natural
#pragma unroll
        for (int rep = 0; rep < 4; rep++) {
            int e = tid + rep * 256;
            int c = e >> 4, d4 = (e & 15) * 4;
            const float* src = &kv[(size_t)(b * Nn + j0 + c) * 128];
            float4 kk4 = *(const float4*)&src[d4];
            KPt[(d4 + 0) * 64 + c] = kk4.x;
            KPt[(d4 + 1) * 64 + c] = kk4.y;
            KPt[(d4 + 2) * 64 + c] = kk4.z;
            KPt[(d4 + 3) * 64 + c] = kk4.w;
            *(float4*)&Vs[c * 64 + d4] = *(const float4*)&src[64 + d4];
        }
        __syncthreads();

        // S = Q @ K^T
        float s[4][4] = {};
#pragma unroll 16
        for (int d = 0; d < 64; d++) {
            float4 a4 = *(const float4*)&Qt[d * 64 + ty * 4];
            float4 b4 = *(const float4*)&KPt[d * 64 + tx * 4];
            float av[4] = {a4.x, a4.y, a4.z, a4.w};
            float bvv[4] = {b4.x, b4.y, b4.z, b4.w};
#pragma unroll
            for (int i = 0; i < 4; i++)
#pragma unroll
                for (int j = 0; j < 4; j++)
                    s[i][j] = fmaf(av[i], bvv[j], s[i][j]);
        }
        // scale + causal mask
        bool diag = (jb == qb);
#pragma unroll
        for (int i = 0; i < 4; i++) {
            int ri = i0 + ty * 4 + i;
#pragma unroll
            for (int j = 0; j < 4; j++) {
                float v = s[i][j] * SCALEf;
                if (diag && (j0 + tx * 4 + j) > ri) v = NEG_HUGE;
                s[i][j] = v;
            }
        }

        __syncthreads();  // done reading Kt before overwriting with P

        // online softmax (rows split across 16 tx lanes)
#pragma unroll
        for (int i = 0; i < 4; i++) {
            float mx = fmaxf(fmaxf(s[i][0], s[i][1]), fmaxf(s[i][2], s[i][3]));
#pragma unroll
            for (int off = 8; off >= 1; off >>= 1)
                mx = fmaxf(mx, __shfl_xor_sync(0xffffffffu, mx, off));
            float nm = fmaxf(m_i[i], mx);
            float alpha = __expf(m_i[i] - nm);
            m_i[i] = nm;
            float p[4];
            float rs = 0.f;
#pragma unroll
            for (int j = 0; j < 4; j++) { p[j] = __expf(s[i][j] - nm); rs += p[j]; }
#pragma unroll
            for (int off = 8; off >= 1; off >>= 1)
                rs += __shfl_xor_sync(0xffffffffu, rs, off);
            l_i[i] = l_i[i] * alpha + rs;
#pragma unroll
            for (int j = 0; j < 4; j++) {
                o[i][j] *= alpha;
                KPt[(tx * 4 + j) * 64 + ty * 4 + i] = p[j];  // Pt[c][r]
            }
        }
        __syncthreads();

        // O += P @ V
#pragma unroll 8
        for (int c = 0; c < 64; c++) {
            float4 a4 = *(const float4*)&KPt[c * 64 + ty * 4];
            float4 b4 = *(const float4*)&Vs[c * 64 + tx * 4];
            float av[4] = {a4.x, a4.y, a4.z, a4.w};
            float bvv[4] = {b4.x, b4.y, b4.z, b4.w};
#pragma unroll
            for (int i = 0; i < 4; i++)
#pragma unroll
                for (int j = 0; j < 4; j++)
                    o[i][j] = fmaf(av[i], bvv[j], o[i][j]);
        }
        __syncthreads();
    }

#pragma unroll
    for (int i = 0; i < 4; i++) {
        float inv = 1.f / l_i[i];
        float4 w;
        w.x = o[i][0] * inv; w.y = o[i][1] * inv;
        w.z = o[i][2] * inv; w.w = o[i][3] * inv;
        *(float4*)&localOut[((size_t)bh * Nn + i0 + ty * 4 + i) * 64 + tx * 4] = w;
    }
}

// ---------------- memory (KNN) attention + gate combine ----------------
// one warp per (b,h,i); streaming online softmax over 33 slots (null + 32)
__global__ void mem_attn_kernel(const float* __restrict__ q,
                                const float* __restrict__ memkv,
                                const float* __restrict__ nullk,
                                const float* __restrict__ nullv,
                                const float* __restrict__ gate,
                                const float* __restrict__ localv,
                                float* __restrict__ comb) {
    int gw = blockIdx.x * 8 + (threadIdx.x >> 5);
    int lane = threadIdx.x & 31;
    int b = gw >> 14;          // / (H*N)
    int rem = gw & 16383;
    int h = rem >> 11;         // / N
    int i = rem & 2047;

    const float* qp = &q[(size_t)(b * Nn + i) * 512 + h * 64];
    float q0 = qp[lane], q1 = qp[lane + 32];

    // null slot first
    float s = q0 * nullk[lane] + q1 * nullk[lane + 32];
#pragma unroll
    for (int off = 16; off >= 1; off >>= 1) s += __shfl_xor_sync(0xffffffffu, s, off);
    s *= SCALEf;
    float m = s, ls = 1.f;
    float a0 = nullv[lane], a1 = nullv[lane + 32];

    size_t base = (size_t)(b * Hh + h) * Nn + i;
    const unsigned char* mp = &g_mask[base * Kk];
    unsigned mbits = __ballot_sync(0xffffffffu, mp[lane] != 0);
    const float* kvp = &memkv[base * (size_t)(Kk * 2 * DHd)];

    for (int kk = 0; kk < Kk; kk++) {
        if (!((mbits >> kk) & 1u)) continue;
        const float* kp = kvp + (size_t)kk * 128;
        float ss = q0 * kp[lane] + q1 * kp[lane + 32];
#pragma unroll
        for (int off = 16; off >= 1; off >>= 1) ss += __shfl_xor_sync(0xffffffffu, ss, off);
        ss *= SCALEf;
        float nm = fmaxf(m, ss);
        float al = __expf(m - nm);
        float p = __expf(ss - nm);
        m = nm;
        ls = ls * al + p;
        a0 = a0 * al + p * kp[64 + lane];
        a1 = a1 * al + p * kp[96 + lane];
    }
    float inv = 1.f / ls;
    float mem0 = a0 * inv, mem1 = a1 * inv;

    float g = 1.f / (1.f + __expf(-gate[h]));
    const float* lp = &localv[base * DHd];
    float* cp = &comb[(size_t)(b * Nn + i) * 512 + h * 64];
    cp[lane]      = lp[lane]      * g + mem0 * (1.f - g);
    cp[lane + 32] = lp[lane + 32] * g + mem1 * (1.f - g);
}

// ---------------- launch ----------------
extern "C" void kernel_launch(void* const* d_in, const int* in_sizes, int n_in,
                              void* d_out, int out_size) {
    const float* x      = (const float*)d_in[0];
    const float* mem_kv = (const float*)d_in[1];
    const void*  m_mask = d_in[2];
    const float* Wq     = (const float*)d_in[3];
    const float* Wkv    = (const float*)d_in[4];
    const float* Wo     = (const float*)d_in[5];
    const float* bo     = (const float*)d_in[6];
    const float* null_k = (const float*)d_in[7];
    const float* null_v = (const float*)d_in[8];
    const float* gate   = (const float*)d_in[9];
    float* out = (float*)d_out;

    float* q_buf;     cudaGetSymbolAddress((void**)&q_buf, g_q);
    float* kv_buf;    cudaGetSymbolAddress((void**)&kv_buf, g_kv);
    float* local_buf; cudaGetSymbolAddress((void**)&local_buf, g_local);
    float* comb_buf;  cudaGetSymbolAddress((void**)&comb_buf, g_comb);

    // mask dtype detect + expand to uint8
    detect_mask_kernel<<<1, 256>>>((const unsigned int*)m_mask);
    expand_mask_kernel<<<(Bb * Hh * Nn * Kk + 255) / 256, 256>>>(m_mask, Bb * Hh * Nn * Kk);

    // projections
    sgemm_kernel<<<dim3(512 / 64, (Bb * Nn) / 64), 256>>>(x, Wq, nullptr, q_buf,
                                                          Bb * Nn, 512, 512);
    sgemm_kernel<<<dim3(128 / 64, (Bb * Nn) / 64), 256>>>(x, Wkv, nullptr, kv_buf,
                                                          Bb * Nn, 128, 512);

    // local causal attention
    flash_local_kernel<<<dim3(Nn / 64, Bb * Hh), 256>>>(q_buf, kv_buf, local_buf);

    // memory attention + gate combine
    mem_attn_kernel<<<(Bb * Hh * Nn) / 8, 256>>>(q_buf, mem_kv, null_k, null_v,
                                                 gate, local_buf, comb_buf);

    // output projection with bias
    sgemm_kernel<<<dim3(512 / 64, (Bb * Nn) / 64), 256>>>(comb_buf, Wo, bo, out,
                                                          Bb * Nn, 512, 512);
}